// round 1
// baseline (speedup 1.0000x reference)
#include <cuda_runtime.h>
#include <cuda_bf16.h>
#include <cstdint>
#include <cstddef>

// ---------------------------------------------------------------------------
// WindowAttention (Swin): B=8192 windows, N=49 tokens, DIM=384, H=12, HD=32
//   qkv = x @ qkv_w^T + qkv_b
//   attn = softmax(q*scale @ k^T + rel_pos_bias + shift_mask)
//   out  = (attn @ v) @ proj_w^T + proj_b
// Round 1: fp32 baseline. 3 kernels:
//   1) SGEMM (M=401408, N=1152, K=384) -> g_qkv scratch
//   2) fused per-(window,head) attention -> g_attn scratch
//   3) SGEMM (M=401408, N=384,  K=384) -> d_out
// ---------------------------------------------------------------------------

#define NWIN      8192
#define NTOK      49
#define DIM       384
#define NHEAD     12
#define HEADD     32
#define NW_IMG    64
#define MROWS     (NWIN * NTOK)        // 401408
#define QKV_COLS  1152
#define SCALE_F   0.17677669529663687f // 1/sqrt(32)

// Device scratch (static allocation — permitted; no runtime alloc).
__device__ float g_qkv[(size_t)MROWS * QKV_COLS];   // ~1.72 GiB
__device__ float g_attn[(size_t)MROWS * DIM];       // ~0.57 GiB

// ---------------------------------------------------------------------------
// SGEMM: C[M][Nn] = A[M][K] * W[Nn][K]^T + bias[Nn]
// BM=BN=128, BK=8, 256 threads, 8x8 per thread, double-buffered smem.
// Requires M%128==0, Nn%128==0, K%8==0 (true for both GEMMs here).
// ---------------------------------------------------------------------------
#define BM 128
#define BN 128
#define BK 8

__global__ __launch_bounds__(256)
void sgemm_bias_kernel(const float* __restrict__ A, const float* __restrict__ W,
                       const float* __restrict__ bias, float* __restrict__ C,
                       int M, int Nn, int K)
{
    __shared__ float As[2][BK][BM];
    __shared__ float Bs[2][BK][BN];

    const int tid = threadIdx.x;
    const int bx = blockIdx.x;   // N-tile
    const int by = blockIdx.y;   // M-tile

    // Global-load mapping: each thread fetches one float4 of A and one of W per chunk
    const int lrow = tid >> 1;          // 0..127
    const int lk4  = (tid & 1) << 2;    // 0 or 4

    const float* Ag = A + (size_t)(by * BM + lrow) * K + lk4;
    const float* Wg = W + (size_t)(bx * BN + lrow) * K + lk4;

    const int tx = tid & 15;   // col group
    const int ty = tid >> 4;   // row group

    float acc[8][8];
    #pragma unroll
    for (int i = 0; i < 8; i++)
        #pragma unroll
        for (int j = 0; j < 8; j++) acc[i][j] = 0.0f;

    // Preload chunk 0
    {
        float4 a4 = *(const float4*)Ag;
        float4 b4 = *(const float4*)Wg;
        As[0][lk4 + 0][lrow] = a4.x; As[0][lk4 + 1][lrow] = a4.y;
        As[0][lk4 + 2][lrow] = a4.z; As[0][lk4 + 3][lrow] = a4.w;
        Bs[0][lk4 + 0][lrow] = b4.x; Bs[0][lk4 + 1][lrow] = b4.y;
        Bs[0][lk4 + 2][lrow] = b4.z; Bs[0][lk4 + 3][lrow] = b4.w;
    }
    __syncthreads();

    const int nt = K / BK;
    for (int kt = 0; kt < nt; ++kt) {
        float4 an, bn;
        const bool has_next = (kt + 1 < nt);
        if (has_next) {
            an = *(const float4*)(Ag + (size_t)(kt + 1) * BK);
            bn = *(const float4*)(Wg + (size_t)(kt + 1) * BK);
        }
        const int buf = kt & 1;
        #pragma unroll
        for (int kk = 0; kk < BK; ++kk) {
            float a[8], b[8];
            *(float4*)&a[0] = *(const float4*)&As[buf][kk][ty * 4];
            *(float4*)&a[4] = *(const float4*)&As[buf][kk][ty * 4 + 64];
            *(float4*)&b[0] = *(const float4*)&Bs[buf][kk][tx * 4];
            *(float4*)&b[4] = *(const float4*)&Bs[buf][kk][tx * 4 + 64];
            #pragma unroll
            for (int i = 0; i < 8; i++)
                #pragma unroll
                for (int j = 0; j < 8; j++)
                    acc[i][j] += a[i] * b[j];
        }
        if (has_next) {
            const int nb = buf ^ 1;
            As[nb][lk4 + 0][lrow] = an.x; As[nb][lk4 + 1][lrow] = an.y;
            As[nb][lk4 + 2][lrow] = an.z; As[nb][lk4 + 3][lrow] = an.w;
            Bs[nb][lk4 + 0][lrow] = bn.x; Bs[nb][lk4 + 1][lrow] = bn.y;
            Bs[nb][lk4 + 2][lrow] = bn.z; Bs[nb][lk4 + 3][lrow] = bn.w;
            __syncthreads();
        }
    }

    // Epilogue: add bias, store two float4 per row-slot
    const int gcol0 = bx * BN + tx * 4;
    float bb[8];
    #pragma unroll
    for (int j = 0; j < 4; j++) {
        bb[j]     = bias[gcol0 + j];
        bb[j + 4] = bias[gcol0 + 64 + j];
    }
    #pragma unroll
    for (int ri = 0; ri < 2; ri++) {
        #pragma unroll
        for (int r = 0; r < 4; r++) {
            const int row = by * BM + ty * 4 + ri * 64 + r;
            const int ai  = ri * 4 + r;
            float* cp = C + (size_t)row * Nn + gcol0;
            float4 o0 = make_float4(acc[ai][0] + bb[0], acc[ai][1] + bb[1],
                                    acc[ai][2] + bb[2], acc[ai][3] + bb[3]);
            float4 o1 = make_float4(acc[ai][4] + bb[4], acc[ai][5] + bb[5],
                                    acc[ai][6] + bb[6], acc[ai][7] + bb[7]);
            *(float4*)cp        = o0;
            *(float4*)(cp + 64) = o1;
        }
    }
}

// ---------------------------------------------------------------------------
// Fused attention kernel: grid (NWIN, NHEAD), 128 threads.
// S stored transposed: S[j][i]  (j = key index, i = query index)
// ---------------------------------------------------------------------------
__global__ __launch_bounds__(128)
void attn_kernel(const float* __restrict__ mask,
                 const float* __restrict__ rel_table,
                 const int*   __restrict__ rel_idx)
{
    __shared__ float q_s[NTOK][36];
    __shared__ float k_s[NTOK][36];
    __shared__ float v_s[NTOK][36];
    __shared__ float S[NTOK][52];   // S[j][i]

    const int w   = blockIdx.x;
    const int h   = blockIdx.y;
    const int tid = threadIdx.x;

    // ---- Load q, k, v tiles (q pre-scaled) ----
    const size_t base0 = (size_t)w * NTOK * QKV_COLS + h * HEADD;
    for (int idx = tid; idx < NTOK * HEADD; idx += 128) {
        const int i = idx >> 5, d = idx & 31;
        const size_t g = base0 + (size_t)i * QKV_COLS + d;
        q_s[i][d] = g_qkv[g] * SCALE_F;
        k_s[i][d] = g_qkv[g + 384];
        v_s[i][d] = g_qkv[g + 768];
    }

    // ---- Pre-seed S with rel-pos bias + shift mask ----
    const float* mrow = mask + (size_t)(w & (NW_IMG - 1)) * (NTOK * NTOK);
    for (int idx = tid; idx < NTOK * NTOK; idx += 128) {
        const int i = idx / NTOK;
        const int j = idx - i * NTOK;
        S[j][i] = rel_table[rel_idx[idx] * NHEAD + h] + mrow[idx];
    }
    __syncthreads();

    // ---- Scores: S[j][i] += q_i . k_j ----
    {
        const int j  = tid & 63;
        const int ig = tid >> 6;    // 0 or 1
        if (j < NTOK) {
            float kreg[HEADD];
            #pragma unroll
            for (int kq = 0; kq < 8; ++kq)
                *(float4*)&kreg[kq * 4] = *(const float4*)&k_s[j][kq * 4];
            const int i0 = ig ? 25 : 0;
            const int i1 = ig ? NTOK : 25;
            for (int i = i0; i < i1; ++i) {
                float acc = 0.0f;
                #pragma unroll
                for (int kq = 0; kq < 8; ++kq) {
                    const float4 q4 = *(const float4*)&q_s[i][kq * 4];
                    acc += q4.x * kreg[kq * 4 + 0];
                    acc += q4.y * kreg[kq * 4 + 1];
                    acc += q4.z * kreg[kq * 4 + 2];
                    acc += q4.w * kreg[kq * 4 + 3];
                }
                S[j][i] += acc;
            }
        }
    }
    __syncthreads();

    // ---- Softmax over j for each row i ----
    if (tid < NTOK) {
        const int i = tid;
        float m = -1e30f;
        for (int j = 0; j < NTOK; ++j) m = fmaxf(m, S[j][i]);
        float sum = 0.0f;
        for (int j = 0; j < NTOK; ++j) {
            const float e = __expf(S[j][i] - m);
            S[j][i] = e;
            sum += e;
        }
        const float inv = 1.0f / sum;
        for (int j = 0; j < NTOK; ++j) S[j][i] *= inv;
    }
    __syncthreads();

    // ---- O[i][d] = sum_j S[j][i] * v[j][d] ----
    {
        const int d  = tid & 31;
        const int ig = tid >> 5;           // warp id: 0..3
        const int i0 = ig * 13;
        const int nrows = (i0 + 13 <= NTOK) ? 13 : (NTOK - i0);  // 13,13,13,10
        float o[13];
        #pragma unroll
        for (int r = 0; r < 13; ++r) o[r] = 0.0f;

        for (int j = 0; j < NTOK; ++j) {
            const float vj = v_s[j][d];
            #pragma unroll
            for (int r = 0; r < 13; ++r)
                if (r < nrows) o[r] += S[j][i0 + r] * vj;
        }
        for (int r = 0; r < nrows; ++r) {
            const size_t gr = ((size_t)(w * NTOK + i0 + r)) * DIM + h * HEADD + d;
            g_attn[gr] = o[r];
        }
    }
}

// ---------------------------------------------------------------------------
// Launch
// ---------------------------------------------------------------------------
extern "C" void kernel_launch(void* const* d_in, const int* in_sizes, int n_in,
                              void* d_out, int out_size)
{
    const float* x         = (const float*)d_in[0];
    const float* mask      = (const float*)d_in[1];
    const float* rel_table = (const float*)d_in[2];
    const float* qkv_w     = (const float*)d_in[3];
    const float* qkv_b     = (const float*)d_in[4];
    const float* proj_w    = (const float*)d_in[5];
    const float* proj_b    = (const float*)d_in[6];
    const int*   rel_idx   = (const int*)d_in[7];
    float*       out       = (float*)d_out;

    void* qkv_ptr  = nullptr;
    void* attn_ptr = nullptr;
    cudaGetSymbolAddress(&qkv_ptr,  g_qkv);
    cudaGetSymbolAddress(&attn_ptr, g_attn);

    // 1) QKV GEMM: (401408 x 384) @ (1152 x 384)^T
    {
        dim3 grid(QKV_COLS / BN, MROWS / BM);   // (9, 3136)
        sgemm_bias_kernel<<<grid, 256>>>(x, qkv_w, qkv_b, (float*)qkv_ptr,
                                         MROWS, QKV_COLS, DIM);
    }

    // 2) Fused attention
    {
        dim3 grid(NWIN, NHEAD);
        attn_kernel<<<grid, 128>>>(mask, rel_table, rel_idx);
    }

    // 3) Output projection GEMM: (401408 x 384) @ (384 x 384)^T
    {
        dim3 grid(DIM / BN, MROWS / BM);        // (3, 3136)
        sgemm_bias_kernel<<<grid, 256>>>((const float*)attn_ptr, proj_w, proj_b, out,
                                         MROWS, DIM, DIM);
    }
}

// round 6
// speedup vs baseline: 2.0037x; 2.0037x over previous
#include <cuda_runtime.h>
#include <cuda_bf16.h>
#include <cstdint>
#include <cstddef>

// ---------------------------------------------------------------------------
// WindowAttention (Swin) on GB300 — Round 6.
// mma.sync (HMMA) bf16 GEMMs with 3-term split (Markidis) as one K-concat:
//   A2 = [hiA | loA | hiA]  (K'=1152)
//   W2 = [hiW | hiW | loW]
//   A2 @ W2^T = hiA.hiW + loA.hiW + hiA.loW  ~= A @ W^T  (drop loA.loW ~1e-5)
// Kernels:
//   1) split x (act layout), qkv_w/proj_w (wgt layout)
//   2) GEMM qkv = x2 @ wqkv2^T + b     (mma.sync bf16, fp32 accum)
//   3) fused window attention (fp32), writes act-layout split bf16
//   4) GEMM out = attn2 @ wproj2^T + b
// ---------------------------------------------------------------------------

#define NWIN      8192
#define NTOK      49
#define DIM       384
#define NHEAD     12
#define HEADD     32
#define NW_IMG    64
#define MROWS     (NWIN * NTOK)        // 401408
#define QKV_COLS  1152
#define K2        1152                 // split K: hi | lo | hi
#define SCALE_F   0.17677669529663687f

// Device scratch
__device__ float         g_qkv[(size_t)MROWS * QKV_COLS];
__device__ __nv_bfloat16 g_x2[(size_t)MROWS * K2];
__device__ __nv_bfloat16 g_attn2[(size_t)MROWS * K2];
__device__ __nv_bfloat16 g_wqkv2[(size_t)QKV_COLS * K2];
__device__ __nv_bfloat16 g_wproj2[(size_t)DIM * K2];

// ---------------------------------------------------------------------------
// Helpers
// ---------------------------------------------------------------------------
__device__ __forceinline__ uint32_t smem_u32(const void* p) {
    uint32_t a;
    asm("{ .reg .u64 t; cvta.to.shared.u64 t, %1; cvt.u32.u64 %0, t; }"
        : "=r"(a) : "l"(p));
    return a;
}

__device__ __forceinline__ void cpa16(uint32_t dst, const void* src) {
    asm volatile("cp.async.cg.shared.global [%0], [%1], 16;"
                 :: "r"(dst), "l"(src));
}

__device__ __forceinline__ void ldsm_x4(uint32_t* r, uint32_t addr) {
    asm volatile("ldmatrix.sync.aligned.m8n8.x4.shared.b16 {%0,%1,%2,%3}, [%4];"
                 : "=r"(r[0]), "=r"(r[1]), "=r"(r[2]), "=r"(r[3])
                 : "r"(addr));
}

__device__ __forceinline__ void mma16816(float* d, const uint32_t* a,
                                         const uint32_t* b) {
    asm volatile(
        "mma.sync.aligned.m16n8k16.row.col.f32.bf16.bf16.f32 "
        "{%0,%1,%2,%3}, {%4,%5,%6,%7}, {%8,%9}, {%0,%1,%2,%3};"
        : "+f"(d[0]), "+f"(d[1]), "+f"(d[2]), "+f"(d[3])
        : "r"(a[0]), "r"(a[1]), "r"(a[2]), "r"(a[3]),
          "r"(b[0]), "r"(b[1]));
}

// ---------------------------------------------------------------------------
// Split kernels: fp32 [rows][384] -> bf16 [rows][1152]
//   act layout: [hi | lo | hi]
//   wgt layout: [hi | hi | lo]
// ---------------------------------------------------------------------------
__global__ void split_act_kernel(const float* __restrict__ in,
                                 __nv_bfloat16* __restrict__ out, long total4)
{
    long idx = (long)blockIdx.x * blockDim.x + threadIdx.x;
    if (idx >= total4) return;
    long r = idx / (DIM / 4);
    int  c4 = (int)(idx - r * (DIM / 4));
    float4 v = *((const float4*)(in + r * DIM) + c4);
    float a[4] = {v.x, v.y, v.z, v.w};
    __nv_bfloat16 hi[4], lo[4];
    #pragma unroll
    for (int i = 0; i < 4; i++) {
        hi[i] = __float2bfloat16(a[i]);
        lo[i] = __float2bfloat16(a[i] - __bfloat162float(hi[i]));
    }
    __nv_bfloat162 h0 = __halves2bfloat162(hi[0], hi[1]);
    __nv_bfloat162 h1 = __halves2bfloat162(hi[2], hi[3]);
    __nv_bfloat162 l0 = __halves2bfloat162(lo[0], lo[1]);
    __nv_bfloat162 l1 = __halves2bfloat162(lo[2], lo[3]);
    __nv_bfloat162* s0 = (__nv_bfloat162*)(out + r * K2 + c4 * 4);
    __nv_bfloat162* s1 = (__nv_bfloat162*)(out + r * K2 + DIM + c4 * 4);
    __nv_bfloat162* s2 = (__nv_bfloat162*)(out + r * K2 + 2 * DIM + c4 * 4);
    s0[0] = h0; s0[1] = h1;      // hi
    s1[0] = l0; s1[1] = l1;      // lo
    s2[0] = h0; s2[1] = h1;      // hi
}

__global__ void split_wgt_kernel(const float* __restrict__ in,
                                 __nv_bfloat16* __restrict__ out, long total4)
{
    long idx = (long)blockIdx.x * blockDim.x + threadIdx.x;
    if (idx >= total4) return;
    long r = idx / (DIM / 4);
    int  c4 = (int)(idx - r * (DIM / 4));
    float4 v = *((const float4*)(in + r * DIM) + c4);
    float a[4] = {v.x, v.y, v.z, v.w};
    __nv_bfloat16 hi[4], lo[4];
    #pragma unroll
    for (int i = 0; i < 4; i++) {
        hi[i] = __float2bfloat16(a[i]);
        lo[i] = __float2bfloat16(a[i] - __bfloat162float(hi[i]));
    }
    __nv_bfloat162 h0 = __halves2bfloat162(hi[0], hi[1]);
    __nv_bfloat162 h1 = __halves2bfloat162(hi[2], hi[3]);
    __nv_bfloat162 l0 = __halves2bfloat162(lo[0], lo[1]);
    __nv_bfloat162 l1 = __halves2bfloat162(lo[2], lo[3]);
    __nv_bfloat162* s0 = (__nv_bfloat162*)(out + r * K2 + c4 * 4);
    __nv_bfloat162* s1 = (__nv_bfloat162*)(out + r * K2 + DIM + c4 * 4);
    __nv_bfloat162* s2 = (__nv_bfloat162*)(out + r * K2 + 2 * DIM + c4 * 4);
    s0[0] = h0; s0[1] = h1;      // hi
    s1[0] = h0; s1[1] = h1;      // hi
    s2[0] = l0; s2[1] = l1;      // lo
}

// ---------------------------------------------------------------------------
// HMMA GEMM: C[M][Nn] = A2[M][1152] @ B2[Nn][1152]^T + bias   (bf16 -> fp32)
// 128x128 tile, BK=64 (128B rows, XOR-8 swizzle), 2-stage cp.async,
// 8 warps (2x4), warp tile 64x32, mma.sync.m16n8k16.
// ---------------------------------------------------------------------------
#define BKC       64
#define NCH       (K2 / BKC)            // 18
#define TILE_BYTES 16384                // 128 rows x 128 bytes
#define STAGE_BYTES (2 * TILE_BYTES)    // A + B
#define GSMEM     (2 * STAGE_BYTES + 128)

__global__ __launch_bounds__(256, 2)
void gemm_mma(const __nv_bfloat16* __restrict__ A,
              const __nv_bfloat16* __restrict__ B,
              const float* __restrict__ bias,
              float* __restrict__ C, int Nn)
{
    extern __shared__ uint8_t smem_raw[];
    const int tid  = threadIdx.x;
    const int warp = tid >> 5;
    const int lane = tid & 31;

    uint32_t sraw  = smem_u32(smem_raw);
    uint32_t sbase = (sraw + 127u) & ~127u;   // 128B align

    const int m0 = blockIdx.y << 7;
    const int n0 = blockIdx.x << 7;

    // -------- global -> shared mapping (per thread, 4 units of 16B each) ----
    const char* Ag = (const char*)(A + (size_t)m0 * K2);
    const char* Bg = (const char*)(B + (size_t)n0 * K2);
    uint32_t sw[4];
    size_t   go[4];
    #pragma unroll
    for (int i = 0; i < 4; i++) {
        int u = i * 256 + tid;
        int r = u >> 3, c = u & 7;
        sw[i] = (uint32_t)(r * 128 + ((c ^ (r & 7)) << 4));
        go[i] = (size_t)r * (K2 * 2) + (size_t)c * 16;
    }

    auto load_chunk = [&](int c, int s) {
        uint32_t ab = sbase + s * STAGE_BYTES;
        uint32_t bb = ab + TILE_BYTES;
        size_t koff = (size_t)c * 128;    // 64 bf16 = 128 bytes
        #pragma unroll
        for (int i = 0; i < 4; i++) {
            cpa16(ab + sw[i], Ag + go[i] + koff);
            cpa16(bb + sw[i], Bg + go[i] + koff);
        }
        asm volatile("cp.async.commit_group;" ::: "memory");
    };

    // -------- warp/fragment geometry ----------------------------------------
    const int wm = warp & 1;          // m offset 0/64
    const int wn = warp >> 1;         // n offset 0/32/64/96
    const int l15 = lane & 15;
    const int lhi = lane >> 4;        // k-half for A ldmatrix
    const int g8  = lane >> 3;        // matrix id for B ldmatrix
    const int l8  = lane & 7;

    int rA[4], rowOffA[4];
    #pragma unroll
    for (int mf = 0; mf < 4; mf++) {
        rA[mf] = wm * 64 + mf * 16 + l15;
        rowOffA[mf] = rA[mf] * 128;
    }
    int rB[2], rowOffB[2];
    #pragma unroll
    for (int p = 0; p < 2; p++) {
        rB[p] = wn * 32 + p * 16 + (g8 >> 1) * 8 + l8;
        rowOffB[p] = rB[p] * 128;
    }

    float acc[4][4][4];
    #pragma unroll
    for (int mf = 0; mf < 4; mf++)
        #pragma unroll
        for (int nf = 0; nf < 4; nf++)
            #pragma unroll
            for (int e = 0; e < 4; e++) acc[mf][nf][e] = 0.0f;

    load_chunk(0, 0);

    for (int c = 0; c < NCH; ++c) {
        if (c + 1 < NCH) {
            load_chunk(c + 1, (c + 1) & 1);
            asm volatile("cp.async.wait_group 1;" ::: "memory");
        } else {
            asm volatile("cp.async.wait_group 0;" ::: "memory");
        }
        __syncthreads();

        const uint32_t aT = sbase + (c & 1) * STAGE_BYTES;
        const uint32_t bT = aT + TILE_BYTES;

        #pragma unroll
        for (int ks = 0; ks < 4; ++ks) {
            uint32_t af[4][4];
            #pragma unroll
            for (int mf = 0; mf < 4; mf++) {
                const int c16 = ks * 2 + lhi;
                ldsm_x4(af[mf], aT + rowOffA[mf] +
                                ((c16 ^ (rA[mf] & 7)) << 4));
            }
            uint32_t bf[2][4];
            #pragma unroll
            for (int p = 0; p < 2; p++) {
                const int c16 = ks * 2 + (g8 & 1);
                ldsm_x4(bf[p], bT + rowOffB[p] +
                               ((c16 ^ (rB[p] & 7)) << 4));
            }
            #pragma unroll
            for (int mf = 0; mf < 4; mf++) {
                mma16816(acc[mf][0], af[mf], &bf[0][0]);
                mma16816(acc[mf][1], af[mf], &bf[0][2]);
                mma16816(acc[mf][2], af[mf], &bf[1][0]);
                mma16816(acc[mf][3], af[mf], &bf[1][2]);
            }
        }
        __syncthreads();
    }

    // -------- epilogue: direct float2 stores + bias -------------------------
    const int colBase = n0 + wn * 32 + 2 * (lane & 3);
    float2 b2[4];
    #pragma unroll
    for (int nf = 0; nf < 4; nf++)
        b2[nf] = *(const float2*)(bias + colBase + nf * 8);

    const int rowBase = m0 + wm * 64 + (lane >> 2);
    #pragma unroll
    for (int mf = 0; mf < 4; mf++) {
        const int r0 = rowBase + mf * 16;
        #pragma unroll
        for (int nf = 0; nf < 4; nf++) {
            const int col = colBase + nf * 8;
            float2 v0 = make_float2(acc[mf][nf][0] + b2[nf].x,
                                    acc[mf][nf][1] + b2[nf].y);
            float2 v1 = make_float2(acc[mf][nf][2] + b2[nf].x,
                                    acc[mf][nf][3] + b2[nf].y);
            *(float2*)(C + (size_t)r0 * Nn + col)       = v0;
            *(float2*)(C + (size_t)(r0 + 8) * Nn + col) = v1;
        }
    }
}

// ---------------------------------------------------------------------------
// Fused attention kernel (fp32): grid (NWIN, NHEAD), 128 threads.
// Writes act-layout split bf16 (hi | lo | hi) into g_attn2.
// ---------------------------------------------------------------------------
__global__ __launch_bounds__(128)
void attn_kernel(const float* __restrict__ mask,
                 const float* __restrict__ rel_table,
                 const int*   __restrict__ rel_idx)
{
    __shared__ float q_s[NTOK][36];
    __shared__ float k_s[NTOK][36];
    __shared__ float v_s[NTOK][36];
    __shared__ float S[NTOK][52];   // S[j][i]

    const int w   = blockIdx.x;
    const int h   = blockIdx.y;
    const int tid = threadIdx.x;

    const size_t base0 = (size_t)w * NTOK * QKV_COLS + h * HEADD;
    for (int idx = tid; idx < NTOK * HEADD; idx += 128) {
        const int i = idx >> 5, d = idx & 31;
        const size_t g = base0 + (size_t)i * QKV_COLS + d;
        q_s[i][d] = g_qkv[g] * SCALE_F;
        k_s[i][d] = g_qkv[g + 384];
        v_s[i][d] = g_qkv[g + 768];
    }

    const float* mrow = mask + (size_t)(w & (NW_IMG - 1)) * (NTOK * NTOK);
    for (int idx = tid; idx < NTOK * NTOK; idx += 128) {
        const int i = idx / NTOK;
        const int j = idx - i * NTOK;
        S[j][i] = rel_table[rel_idx[idx] * NHEAD + h] + mrow[idx];
    }
    __syncthreads();

    {
        const int j  = tid & 63;
        const int ig = tid >> 6;
        if (j < NTOK) {
            float kreg[HEADD];
            #pragma unroll
            for (int kq = 0; kq < 8; ++kq)
                *(float4*)&kreg[kq * 4] = *(const float4*)&k_s[j][kq * 4];
            const int i0 = ig ? 25 : 0;
            const int i1 = ig ? NTOK : 25;
            for (int i = i0; i < i1; ++i) {
                float acc = 0.0f;
                #pragma unroll
                for (int kq = 0; kq < 8; ++kq) {
                    const float4 q4 = *(const float4*)&q_s[i][kq * 4];
                    acc += q4.x * kreg[kq * 4 + 0];
                    acc += q4.y * kreg[kq * 4 + 1];
                    acc += q4.z * kreg[kq * 4 + 2];
                    acc += q4.w * kreg[kq * 4 + 3];
                }
                S[j][i] += acc;
            }
        }
    }
    __syncthreads();

    if (tid < NTOK) {
        const int i = tid;
        float m = -1e30f;
        for (int j = 0; j < NTOK; ++j) m = fmaxf(m, S[j][i]);
        float sum = 0.0f;
        for (int j = 0; j < NTOK; ++j) {
            const float e = __expf(S[j][i] - m);
            S[j][i] = e;
            sum += e;
        }
        const float inv = 1.0f / sum;
        for (int j = 0; j < NTOK; ++j) S[j][i] *= inv;
    }
    __syncthreads();

    {
        const int d  = tid & 31;
        const int ig = tid >> 5;
        const int i0 = ig * 13;
        const int nrows = (i0 + 13 <= NTOK) ? 13 : (NTOK - i0);
        float o[13];
        #pragma unroll
        for (int r = 0; r < 13; ++r) o[r] = 0.0f;

        for (int j = 0; j < NTOK; ++j) {
            const float vj = v_s[j][d];
            #pragma unroll
            for (int r = 0; r < 13; ++r)
                if (r < nrows) o[r] += S[j][i0 + r] * vj;
        }
        for (int r = 0; r < nrows; ++r) {
            const size_t rowg = (size_t)(w * NTOK + i0 + r);
            const size_t base = rowg * K2 + h * HEADD + d;
            const float val = o[r];
            const __nv_bfloat16 hi = __float2bfloat16(val);
            const __nv_bfloat16 lo =
                __float2bfloat16(val - __bfloat162float(hi));
            g_attn2[base]           = hi;   // segment 0: hi
            g_attn2[base + DIM]     = lo;   // segment 1: lo
            g_attn2[base + 2 * DIM] = hi;   // segment 2: hi
        }
    }
}

// ---------------------------------------------------------------------------
// Launch
// ---------------------------------------------------------------------------
extern "C" void kernel_launch(void* const* d_in, const int* in_sizes, int n_in,
                              void* d_out, int out_size)
{
    const float* x         = (const float*)d_in[0];
    const float* mask      = (const float*)d_in[1];
    const float* rel_table = (const float*)d_in[2];
    const float* qkv_w     = (const float*)d_in[3];
    const float* qkv_b     = (const float*)d_in[4];
    const float* proj_w    = (const float*)d_in[5];
    const float* proj_b    = (const float*)d_in[6];
    const int*   rel_idx   = (const int*)d_in[7];
    float*       out       = (float*)d_out;

    void *qkv_p, *x2_p, *attn2_p, *wq2_p, *wp2_p;
    cudaGetSymbolAddress(&qkv_p,   g_qkv);
    cudaGetSymbolAddress(&x2_p,    g_x2);
    cudaGetSymbolAddress(&attn2_p, g_attn2);
    cudaGetSymbolAddress(&wq2_p,   g_wqkv2);
    cudaGetSymbolAddress(&wp2_p,   g_wproj2);

    cudaFuncSetAttribute(gemm_mma,
                         cudaFuncAttributeMaxDynamicSharedMemorySize, GSMEM);

    // Splits
    {
        long t4 = (long)MROWS * (DIM / 4);
        split_act_kernel<<<(unsigned)((t4 + 255) / 256), 256>>>(
            x, (__nv_bfloat16*)x2_p, t4);
    }
    {
        long t4 = (long)QKV_COLS * (DIM / 4);
        split_wgt_kernel<<<(unsigned)((t4 + 255) / 256), 256>>>(
            qkv_w, (__nv_bfloat16*)wq2_p, t4);
    }
    {
        long t4 = (long)DIM * (DIM / 4);
        split_wgt_kernel<<<(unsigned)((t4 + 255) / 256), 256>>>(
            proj_w, (__nv_bfloat16*)wp2_p, t4);
    }

    // 1) QKV GEMM (HMMA)
    {
        dim3 grid(QKV_COLS / 128, MROWS / 128);    // (9, 3136)
        gemm_mma<<<grid, 256, GSMEM>>>(
            (const __nv_bfloat16*)x2_p, (const __nv_bfloat16*)wq2_p,
            qkv_b, (float*)qkv_p, QKV_COLS);
    }

    // 2) Fused attention
    {
        dim3 grid(NWIN, NHEAD);
        attn_kernel<<<grid, 128>>>(mask, rel_table, rel_idx);
    }

    // 3) Output projection GEMM (HMMA)
    {
        dim3 grid(DIM / 128, MROWS / 128);         // (3, 3136)
        gemm_mma<<<grid, 256, GSMEM>>>(
            (const __nv_bfloat16*)attn2_p, (const __nv_bfloat16*)wp2_p,
            proj_b, out, DIM);
    }
}

// round 8
// speedup vs baseline: 2.4090x; 1.2023x over previous
#include <cuda_runtime.h>
#include <cuda_fp16.h>
#include <cstdint>
#include <cstddef>

// ---------------------------------------------------------------------------
// WindowAttention (Swin) on GB300 — Round 8 (R7 resubmit after infra flake).
// mma.sync (HMMA) fp16 GEMMs with 2-term split as one K-concat:
//   A2 = [hiA | loA]  (fp16, K'=768)
//   W2 = [hiW | hiW]  (fp16)
//   A2 @ W2^T = (hiA+loA).hiW = A.hiW  => only error is A.loW ~ 2^-12 rel.
// Kernels:
//   1) split x (act: hi|lo), qkv_w/proj_w (wgt: hi|hi)
//   2) GEMM qkv = x2 @ wqkv2^T + b     (mma.sync f16, fp32 accum)
//   3) fused window attention (fp32), writes act-layout split fp16
//   4) GEMM out = attn2 @ wproj2^T + b
// ---------------------------------------------------------------------------

#define NWIN      8192
#define NTOK      49
#define DIM       384
#define NHEAD     12
#define HEADD     32
#define NW_IMG    64
#define MROWS     (NWIN * NTOK)        // 401408
#define QKV_COLS  1152
#define K2        768                  // split K: hi | lo
#define SCALE_F   0.17677669529663687f

// Device scratch
__device__ float  g_qkv[(size_t)MROWS * QKV_COLS];
__device__ __half g_x2[(size_t)MROWS * K2];
__device__ __half g_attn2[(size_t)MROWS * K2];
__device__ __half g_wqkv2[(size_t)QKV_COLS * K2];
__device__ __half g_wproj2[(size_t)DIM * K2];

// ---------------------------------------------------------------------------
// Helpers
// ---------------------------------------------------------------------------
__device__ __forceinline__ uint32_t smem_u32(const void* p) {
    uint32_t a;
    asm("{ .reg .u64 t; cvta.to.shared.u64 t, %1; cvt.u32.u64 %0, t; }"
        : "=r"(a) : "l"(p));
    return a;
}

__device__ __forceinline__ void cpa16(uint32_t dst, const void* src) {
    asm volatile("cp.async.cg.shared.global [%0], [%1], 16;"
                 :: "r"(dst), "l"(src));
}

__device__ __forceinline__ void ldsm_x4(uint32_t* r, uint32_t addr) {
    asm volatile("ldmatrix.sync.aligned.m8n8.x4.shared.b16 {%0,%1,%2,%3}, [%4];"
                 : "=r"(r[0]), "=r"(r[1]), "=r"(r[2]), "=r"(r[3])
                 : "r"(addr));
}

__device__ __forceinline__ void mma16816(float* d, const uint32_t* a,
                                         const uint32_t* b) {
    asm volatile(
        "mma.sync.aligned.m16n8k16.row.col.f32.f16.f16.f32 "
        "{%0,%1,%2,%3}, {%4,%5,%6,%7}, {%8,%9}, {%0,%1,%2,%3};"
        : "+f"(d[0]), "+f"(d[1]), "+f"(d[2]), "+f"(d[3])
        : "r"(a[0]), "r"(a[1]), "r"(a[2]), "r"(a[3]),
          "r"(b[0]), "r"(b[1]));
}

// ---------------------------------------------------------------------------
// Split kernels: fp32 [rows][384] -> fp16 [rows][768]
//   act layout: [hi | lo]
//   wgt layout: [hi | hi]
// ---------------------------------------------------------------------------
__global__ void split_act_kernel(const float* __restrict__ in,
                                 __half* __restrict__ out, long total4)
{
    long idx = (long)blockIdx.x * blockDim.x + threadIdx.x;
    if (idx >= total4) return;
    long r = idx / (DIM / 4);
    int  c4 = (int)(idx - r * (DIM / 4));
    float4 v = *((const float4*)(in + r * DIM) + c4);
    float a[4] = {v.x, v.y, v.z, v.w};
    __half hi[4], lo[4];
    #pragma unroll
    for (int i = 0; i < 4; i++) {
        hi[i] = __float2half_rn(a[i]);
        lo[i] = __float2half_rn(a[i] - __half2float(hi[i]));
    }
    __half2* s0 = (__half2*)(out + r * K2 + c4 * 4);
    __half2* s1 = (__half2*)(out + r * K2 + DIM + c4 * 4);
    s0[0] = __halves2half2(hi[0], hi[1]);
    s0[1] = __halves2half2(hi[2], hi[3]);
    s1[0] = __halves2half2(lo[0], lo[1]);
    s1[1] = __halves2half2(lo[2], lo[3]);
}

__global__ void split_wgt_kernel(const float* __restrict__ in,
                                 __half* __restrict__ out, long total4)
{
    long idx = (long)blockIdx.x * blockDim.x + threadIdx.x;
    if (idx >= total4) return;
    long r = idx / (DIM / 4);
    int  c4 = (int)(idx - r * (DIM / 4));
    float4 v = *((const float4*)(in + r * DIM) + c4);
    float a[4] = {v.x, v.y, v.z, v.w};
    __half hi[4];
    #pragma unroll
    for (int i = 0; i < 4; i++) hi[i] = __float2half_rn(a[i]);
    __half2 h0 = __halves2half2(hi[0], hi[1]);
    __half2 h1 = __halves2half2(hi[2], hi[3]);
    __half2* s0 = (__half2*)(out + r * K2 + c4 * 4);
    __half2* s1 = (__half2*)(out + r * K2 + DIM + c4 * 4);
    s0[0] = h0; s0[1] = h1;      // hi
    s1[0] = h0; s1[1] = h1;      // hi (duplicate)
}

// ---------------------------------------------------------------------------
// HMMA GEMM: C[M][Nn] = A2[M][768] @ B2[Nn][768]^T + bias   (fp16 -> fp32)
// 128x128 tile, BK=64 (128B rows, XOR-8 swizzle), 2-stage cp.async,
// 8 warps (2x4), warp tile 64x32, mma.sync.m16n8k16.
// ---------------------------------------------------------------------------
#define BKC       64
#define NCH       (K2 / BKC)            // 12
#define TILE_BYTES 16384                // 128 rows x 128 bytes
#define STAGE_BYTES (2 * TILE_BYTES)    // A + B
#define GSMEM     (2 * STAGE_BYTES + 128)

__global__ __launch_bounds__(256, 2)
void gemm_mma(const __half* __restrict__ A,
              const __half* __restrict__ B,
              const float* __restrict__ bias,
              float* __restrict__ C, int Nn)
{
    extern __shared__ uint8_t smem_raw[];
    const int tid  = threadIdx.x;
    const int warp = tid >> 5;
    const int lane = tid & 31;

    uint32_t sraw  = smem_u32(smem_raw);
    uint32_t sbase = (sraw + 127u) & ~127u;   // 128B align

    const int m0 = blockIdx.y << 7;
    const int n0 = blockIdx.x << 7;

    // -------- global -> shared mapping (per thread, 4 units of 16B each) ----
    const char* Ag = (const char*)(A + (size_t)m0 * K2);
    const char* Bg = (const char*)(B + (size_t)n0 * K2);
    uint32_t sw[4];
    size_t   go[4];
    #pragma unroll
    for (int i = 0; i < 4; i++) {
        int u = i * 256 + tid;
        int r = u >> 3, c = u & 7;
        sw[i] = (uint32_t)(r * 128 + ((c ^ (r & 7)) << 4));
        go[i] = (size_t)r * (K2 * 2) + (size_t)c * 16;
    }

    auto load_chunk = [&](int c, int s) {
        uint32_t ab = sbase + s * STAGE_BYTES;
        uint32_t bb = ab + TILE_BYTES;
        size_t koff = (size_t)c * 128;    // 64 fp16 = 128 bytes
        #pragma unroll
        for (int i = 0; i < 4; i++) {
            cpa16(ab + sw[i], Ag + go[i] + koff);
            cpa16(bb + sw[i], Bg + go[i] + koff);
        }
        asm volatile("cp.async.commit_group;" ::: "memory");
    };

    // -------- warp/fragment geometry ----------------------------------------
    const int wm = warp & 1;          // m offset 0/64
    const int wn = warp >> 1;         // n offset 0/32/64/96
    const int l15 = lane & 15;
    const int lhi = lane >> 4;        // k-half for A ldmatrix
    const int g8  = lane >> 3;        // matrix id for B ldmatrix
    const int l8  = lane & 7;

    int rA[4], rowOffA[4];
    #pragma unroll
    for (int mf = 0; mf < 4; mf++) {
        rA[mf] = wm * 64 + mf * 16 + l15;
        rowOffA[mf] = rA[mf] * 128;
    }
    int rB[2], rowOffB[2];
    #pragma unroll
    for (int p = 0; p < 2; p++) {
        rB[p] = wn * 32 + p * 16 + (g8 >> 1) * 8 + l8;
        rowOffB[p] = rB[p] * 128;
    }

    float acc[4][4][4];
    #pragma unroll
    for (int mf = 0; mf < 4; mf++)
        #pragma unroll
        for (int nf = 0; nf < 4; nf++)
            #pragma unroll
            for (int e = 0; e < 4; e++) acc[mf][nf][e] = 0.0f;

    load_chunk(0, 0);

    for (int c = 0; c < NCH; ++c) {
        if (c + 1 < NCH) {
            load_chunk(c + 1, (c + 1) & 1);
            asm volatile("cp.async.wait_group 1;" ::: "memory");
        } else {
            asm volatile("cp.async.wait_group 0;" ::: "memory");
        }
        __syncthreads();

        const uint32_t aT = sbase + (c & 1) * STAGE_BYTES;
        const uint32_t bT = aT + TILE_BYTES;

        #pragma unroll
        for (int ks = 0; ks < 4; ++ks) {
            uint32_t af[4][4];
            #pragma unroll
            for (int mf = 0; mf < 4; mf++) {
                const int c16 = ks * 2 + lhi;
                ldsm_x4(af[mf], aT + rowOffA[mf] +
                                ((c16 ^ (rA[mf] & 7)) << 4));
            }
            uint32_t bf[2][4];
            #pragma unroll
            for (int p = 0; p < 2; p++) {
                const int c16 = ks * 2 + (g8 & 1);
                ldsm_x4(bf[p], bT + rowOffB[p] +
                               ((c16 ^ (rB[p] & 7)) << 4));
            }
            #pragma unroll
            for (int mf = 0; mf < 4; mf++) {
                mma16816(acc[mf][0], af[mf], &bf[0][0]);
                mma16816(acc[mf][1], af[mf], &bf[0][2]);
                mma16816(acc[mf][2], af[mf], &bf[1][0]);
                mma16816(acc[mf][3], af[mf], &bf[1][2]);
            }
        }
        __syncthreads();
    }

    // -------- epilogue: direct float2 stores + bias -------------------------
    const int colBase = n0 + wn * 32 + 2 * (lane & 3);
    float2 b2[4];
    #pragma unroll
    for (int nf = 0; nf < 4; nf++)
        b2[nf] = *(const float2*)(bias + colBase + nf * 8);

    const int rowBase = m0 + wm * 64 + (lane >> 2);
    #pragma unroll
    for (int mf = 0; mf < 4; mf++) {
        const int r0 = rowBase + mf * 16;
        #pragma unroll
        for (int nf = 0; nf < 4; nf++) {
            const int col = colBase + nf * 8;
            float2 v0 = make_float2(acc[mf][nf][0] + b2[nf].x,
                                    acc[mf][nf][1] + b2[nf].y);
            float2 v1 = make_float2(acc[mf][nf][2] + b2[nf].x,
                                    acc[mf][nf][3] + b2[nf].y);
            *(float2*)(C + (size_t)r0 * Nn + col)       = v0;
            *(float2*)(C + (size_t)(r0 + 8) * Nn + col) = v1;
        }
    }
}

// ---------------------------------------------------------------------------
// Fused attention kernel (fp32): grid (NWIN, NHEAD), 128 threads.
// Writes act-layout split fp16 (hi | lo) into g_attn2.
// ---------------------------------------------------------------------------
__global__ __launch_bounds__(128)
void attn_kernel(const float* __restrict__ mask,
                 const float* __restrict__ rel_table,
                 const int*   __restrict__ rel_idx)
{
    __shared__ float q_s[NTOK][36];
    __shared__ float k_s[NTOK][36];
    __shared__ float v_s[NTOK][36];
    __shared__ float S[NTOK][52];   // S[j][i]

    const int w   = blockIdx.x;
    const int h   = blockIdx.y;
    const int tid = threadIdx.x;

    const size_t base0 = (size_t)w * NTOK * QKV_COLS + h * HEADD;
    for (int idx = tid; idx < NTOK * HEADD; idx += 128) {
        const int i = idx >> 5, d = idx & 31;
        const size_t g = base0 + (size_t)i * QKV_COLS + d;
        q_s[i][d] = g_qkv[g] * SCALE_F;
        k_s[i][d] = g_qkv[g + 384];
        v_s[i][d] = g_qkv[g + 768];
    }

    const float* mrow = mask + (size_t)(w & (NW_IMG - 1)) * (NTOK * NTOK);
    for (int idx = tid; idx < NTOK * NTOK; idx += 128) {
        const int i = idx / NTOK;
        const int j = idx - i * NTOK;
        S[j][i] = rel_table[rel_idx[idx] * NHEAD + h] + mrow[idx];
    }
    __syncthreads();

    {
        const int j  = tid & 63;
        const int ig = tid >> 6;
        if (j < NTOK) {
            float kreg[HEADD];
            #pragma unroll
            for (int kq = 0; kq < 8; ++kq)
                *(float4*)&kreg[kq * 4] = *(const float4*)&k_s[j][kq * 4];
            const int i0 = ig ? 25 : 0;
            const int i1 = ig ? NTOK : 25;
            for (int i = i0; i < i1; ++i) {
                float acc = 0.0f;
                #pragma unroll
                for (int kq = 0; kq < 8; ++kq) {
                    const float4 q4 = *(const float4*)&q_s[i][kq * 4];
                    acc += q4.x * kreg[kq * 4 + 0];
                    acc += q4.y * kreg[kq * 4 + 1];
                    acc += q4.z * kreg[kq * 4 + 2];
                    acc += q4.w * kreg[kq * 4 + 3];
                }
                S[j][i] += acc;
            }
        }
    }
    __syncthreads();

    if (tid < NTOK) {
        const int i = tid;
        float m = -1e30f;
        for (int j = 0; j < NTOK; ++j) m = fmaxf(m, S[j][i]);
        float sum = 0.0f;
        for (int j = 0; j < NTOK; ++j) {
            const float e = __expf(S[j][i] - m);
            S[j][i] = e;
            sum += e;
        }
        const float inv = 1.0f / sum;
        for (int j = 0; j < NTOK; ++j) S[j][i] *= inv;
    }
    __syncthreads();

    {
        const int d  = tid & 31;
        const int ig = tid >> 5;
        const int i0 = ig * 13;
        const int nrows = (i0 + 13 <= NTOK) ? 13 : (NTOK - i0);
        float o[13];
        #pragma unroll
        for (int r = 0; r < 13; ++r) o[r] = 0.0f;

        for (int j = 0; j < NTOK; ++j) {
            const float vj = v_s[j][d];
            #pragma unroll
            for (int r = 0; r < 13; ++r)
                if (r < nrows) o[r] += S[j][i0 + r] * vj;
        }
        for (int r = 0; r < nrows; ++r) {
            const size_t rowg = (size_t)(w * NTOK + i0 + r);
            const size_t base = rowg * K2 + h * HEADD + d;
            const float val = o[r];
            const __half hi = __float2half_rn(val);
            const __half lo = __float2half_rn(val - __half2float(hi));
            g_attn2[base]       = hi;   // segment 0: hi
            g_attn2[base + DIM] = lo;   // segment 1: lo
        }
    }
}

// ---------------------------------------------------------------------------
// Launch
// ---------------------------------------------------------------------------
extern "C" void kernel_launch(void* const* d_in, const int* in_sizes, int n_in,
                              void* d_out, int out_size)
{
    const float* x         = (const float*)d_in[0];
    const float* mask      = (const float*)d_in[1];
    const float* rel_table = (const float*)d_in[2];
    const float* qkv_w     = (const float*)d_in[3];
    const float* qkv_b     = (const float*)d_in[4];
    const float* proj_w    = (const float*)d_in[5];
    const float* proj_b    = (const float*)d_in[6];
    const int*   rel_idx   = (const int*)d_in[7];
    float*       out       = (float*)d_out;

    void *qkv_p, *x2_p, *attn2_p, *wq2_p, *wp2_p;
    cudaGetSymbolAddress(&qkv_p,   g_qkv);
    cudaGetSymbolAddress(&x2_p,    g_x2);
    cudaGetSymbolAddress(&attn2_p, g_attn2);
    cudaGetSymbolAddress(&wq2_p,   g_wqkv2);
    cudaGetSymbolAddress(&wp2_p,   g_wproj2);

    cudaFuncSetAttribute(gemm_mma,
                         cudaFuncAttributeMaxDynamicSharedMemorySize, GSMEM);

    // Splits
    {
        long t4 = (long)MROWS * (DIM / 4);
        split_act_kernel<<<(unsigned)((t4 + 255) / 256), 256>>>(
            x, (__half*)x2_p, t4);
    }
    {
        long t4 = (long)QKV_COLS * (DIM / 4);
        split_wgt_kernel<<<(unsigned)((t4 + 255) / 256), 256>>>(
            qkv_w, (__half*)wq2_p, t4);
    }
    {
        long t4 = (long)DIM * (DIM / 4);
        split_wgt_kernel<<<(unsigned)((t4 + 255) / 256), 256>>>(
            proj_w, (__half*)wp2_p, t4);
    }

    // 1) QKV GEMM (HMMA fp16)
    {
        dim3 grid(QKV_COLS / 128, MROWS / 128);    // (9, 3136)
        gemm_mma<<<grid, 256, GSMEM>>>(
            (const __half*)x2_p, (const __half*)wq2_p,
            qkv_b, (float*)qkv_p, QKV_COLS);
    }

    // 2) Fused attention
    {
        dim3 grid(NWIN, NHEAD);
        attn_kernel<<<grid, 128>>>(mask, rel_table, rel_idx);
    }

    // 3) Output projection GEMM (HMMA fp16)
    {
        dim3 grid(DIM / 128, MROWS / 128);         // (3, 3136)
        gemm_mma<<<grid, 256, GSMEM>>>(
            (const __half*)attn2_p, (const __half*)wp2_p,
            proj_b, out, DIM);
    }
}